// round 10
// baseline (speedup 1.0000x reference)
#include <cuda_runtime.h>
#include <cuda_fp16.h>
#include <cstdint>

#define B_   16
#define C_   512
#define HW_  4096
#define W64  64
#define WD_  512
#define EPS_ 1e-6f
#define NT_  16384           // total Winograd tiles = B_ * 1024
#define NCF  16              // Winograd coefficients (4x4)

// ---------------- scratch (__device__ globals; no runtime alloc) ----------------
__device__ float  g_style[B_ * C_];
__device__ float  g_S[C_ * C_];
__device__ float  g_rdenom[B_ * C_];
__device__ __half g_U[(size_t)NCF * C_ * C_];        // (coef, oc, ic) fp16
__device__ __half g_V[(size_t)NCF * NT_ * C_];       // (coef, n, ic)  fp16
__device__ __half g_M[(size_t)NCF * C_ * NT_];       // (coef, oc, n)  fp16

// ---------------- helpers ----------------
__device__ __forceinline__ uint32_t smem_u32(const void* p) {
    uint32_t a;
    asm("{ .reg .u64 t; cvta.to.shared.u64 t, %1; cvt.u32.u64 %0, t; }" : "=r"(a) : "l"(p));
    return a;
}
__device__ __forceinline__ void cp16(uint32_t dst, const void* src) {
    asm volatile("cp.async.cg.shared.global [%0], [%1], 16;" :: "r"(dst), "l"(src));
}
template <int N>
__device__ __forceinline__ void cp_wait() {
    asm volatile("cp.async.wait_group %0;" :: "n"(N) : "memory");
}
__device__ __forceinline__ void cp_commit() {
    asm volatile("cp.async.commit_group;" ::: "memory");
}
__device__ __forceinline__ void ldsm4(uint32_t* r, uint32_t addr) {
    asm volatile("ldmatrix.sync.aligned.m8n8.x4.shared.b16 {%0,%1,%2,%3}, [%4];"
                 : "=r"(r[0]), "=r"(r[1]), "=r"(r[2]), "=r"(r[3]) : "r"(addr));
}
__device__ __forceinline__ void mma_f16(float* d, const uint32_t* a, const uint32_t* bf) {
    asm volatile(
        "mma.sync.aligned.m16n8k16.row.col.f32.f16.f16.f32 "
        "{%0,%1,%2,%3}, {%4,%5,%6,%7}, {%8,%9}, {%0,%1,%2,%3};"
        : "+f"(d[0]), "+f"(d[1]), "+f"(d[2]), "+f"(d[3])
        : "r"(a[0]), "r"(a[1]), "r"(a[2]), "r"(a[3]), "r"(bf[0]), "r"(bf[1]));
}

// ---------------- prologue: style / S / rdenom ----------------
__global__ void style_kernel(const float* __restrict__ w, const float* __restrict__ lw,
                             const float* __restrict__ lb) {
    __shared__ float ws[WD_];
    int b = blockIdx.x, o = threadIdx.x;
    ws[o] = w[b * WD_ + o];
    __syncthreads();
    const float* lwr = lw + (size_t)o * WD_;
    float acc = lb[o];
#pragma unroll 8
    for (int d = 0; d < WD_; d++) acc = fmaf(ws[d], lwr[d], acc);
    g_style[b * C_ + o] = acc;
}

__global__ void s_kernel(const float* __restrict__ cw) {
    int o = blockIdx.x, i = threadIdx.x;
    const float* p = cw + ((size_t)o * C_ + i) * 9;
    float s = 0.f;
#pragma unroll
    for (int k = 0; k < 9; k++) { float v = p[k]; s = fmaf(v, v, s); }
    g_S[o * C_ + i] = s;
}

__global__ void rdenom_kernel() {
    __shared__ float st2[C_];
    int b = blockIdx.x, o = threadIdx.x;
    float s = g_style[b * C_ + o];
    st2[o] = s * s;
    __syncthreads();
    const float* Sr = g_S + (size_t)o * C_;
    float acc = EPS_;
#pragma unroll 8
    for (int i = 0; i < C_; i++) acc = fmaf(Sr[i], st2[i], acc);
    g_rdenom[b * C_ + o] = rsqrtf(acc);
}

// ---------------- Winograd weight transform: U = G g G^T ----------------
__global__ void wino_w_kernel(const float* __restrict__ cw) {
    int o = blockIdx.x, i = threadIdx.x;
    const float* g = cw + ((size_t)o * C_ + i) * 9;
    float q[3][3];
#pragma unroll
    for (int r = 0; r < 3; r++)
#pragma unroll
        for (int c = 0; c < 3; c++) q[r][c] = g[r * 3 + c];
    float t[4][3];
#pragma unroll
    for (int c = 0; c < 3; c++) {
        t[0][c] = q[0][c];
        t[1][c] = 0.5f * (q[0][c] + q[1][c] + q[2][c]);
        t[2][c] = 0.5f * (q[0][c] - q[1][c] + q[2][c]);
        t[3][c] = q[2][c];
    }
#pragma unroll
    for (int r = 0; r < 4; r++) {
        float u0 = t[r][0];
        float u1 = 0.5f * (t[r][0] + t[r][1] + t[r][2]);
        float u2 = 0.5f * (t[r][0] - t[r][1] + t[r][2]);
        float u3 = t[r][2];
        g_U[((size_t)(r * 4 + 0) * C_ + o) * C_ + i] = __float2half_rn(u0);
        g_U[((size_t)(r * 4 + 1) * C_ + o) * C_ + i] = __float2half_rn(u1);
        g_U[((size_t)(r * 4 + 2) * C_ + o) * C_ + i] = __float2half_rn(u2);
        g_U[((size_t)(r * 4 + 3) * C_ + o) * C_ + i] = __float2half_rn(u3);
    }
}

// ---------------- Winograd input transform: V = B^T d B (style folded) ----------------
__global__ void __launch_bounds__(256)
wino_x_kernel(const float* __restrict__ x) {
    __shared__ float xs[4][32][71];
    const int b = blockIdx.z, chg = blockIdx.y * 32, ty = blockIdx.x;
    const int tid = threadIdx.x;

    for (int idx = tid; idx < 4 * 32 * 68; idx += 256) {
        int r   = idx / (32 * 68);
        int rem = idx % (32 * 68);
        int ch  = rem / 68;
        int col = rem % 68;
        if (col < 66) {
            int y  = ty * 2 - 1 + r;
            int xg = col - 1;
            float v = 0.f;
            if ((unsigned)y < W64 && (unsigned)xg < W64)
                v = x[((size_t)(b * C_ + chg + ch)) * HW_ + y * W64 + xg];
            xs[r][ch][col] = v;
        }
    }
    __syncthreads();

    const int tx  = tid >> 3;          // 0..31 tile col
    const int ch4 = (tid & 7) * 4;     // 0,4,...,28
    const int n   = b * 1024 + ty * 32 + tx;

    unsigned short hs[NCF][4];
#pragma unroll
    for (int cc = 0; cc < 4; cc++) {
        const int ch = ch4 + cc;
        const float st = g_style[b * C_ + chg + ch];
        float d[4][4];
#pragma unroll
        for (int r = 0; r < 4; r++)
#pragma unroll
            for (int c = 0; c < 4; c++) d[r][c] = xs[r][ch][2 * tx + c];
        float wv[4][4];
#pragma unroll
        for (int c = 0; c < 4; c++) {
            wv[0][c] = d[0][c] - d[2][c];
            wv[1][c] = d[1][c] + d[2][c];
            wv[2][c] = d[2][c] - d[1][c];
            wv[3][c] = d[1][c] - d[3][c];
        }
#pragma unroll
        for (int r = 0; r < 4; r++) {
            float v0 = wv[r][0] - wv[r][2];
            float v1 = wv[r][1] + wv[r][2];
            float v2 = wv[r][2] - wv[r][1];
            float v3 = wv[r][1] - wv[r][3];
            hs[r * 4 + 0][cc] = __half_as_ushort(__float2half_rn(v0 * st));
            hs[r * 4 + 1][cc] = __half_as_ushort(__float2half_rn(v1 * st));
            hs[r * 4 + 2][cc] = __half_as_ushort(__float2half_rn(v2 * st));
            hs[r * 4 + 3][cc] = __half_as_ushort(__float2half_rn(v3 * st));
        }
    }
#pragma unroll
    for (int c = 0; c < NCF; c++) {
        uint2 val;
        val.x = (uint32_t)hs[c][0] | ((uint32_t)hs[c][1] << 16);
        val.y = (uint32_t)hs[c][2] | ((uint32_t)hs[c][3] << 16);
        *(uint2*)(g_V + ((size_t)c * NT_ + n) * C_ + chg + ch4) = val;
    }
}

// ---------------- Winograd GEMM: 4 coefs per CTA, continuous pipeline ----------------
// CTA 128 oc x 128 n; per coef K = 512 (16 chunks of 32ch); 64 iterations total.
// 8 warps (wm2 x wn4), warp tile 64x32 = 4x4 m16n8k16 x 2 ksteps.
// 3-stage cp.async ring, two syncs per iteration (R5/R6 proven structure).
#define STR    40
#define TILE_H (128 * STR)                 // 5120 halves per tile
#define STAGE_B (2 * TILE_H * 2)           // A + B per stage = 20480 bytes
#define NSTAGE 3
#define SMEM_BYTES (NSTAGE * STAGE_B)      // 61440
#define CPC    4                           // coefs per CTA
#define NITER  (CPC * 16)                  // 64

__global__ void __launch_bounds__(256, 2)
wino_gemm_kernel() {
    extern __shared__ __half smh[];
    const int tid  = threadIdx.x;
    const int cg   = blockIdx.z;           // coef group: coefs cg*4 .. cg*4+3
    const int oc0  = blockIdx.y * 128;
    const int n0   = blockIdx.x * 128;
    const int lane = tid & 31;
    const int wrp  = tid >> 5;
    const int wm   = wrp & 1;
    const int wn   = wrp >> 1;
    const int qr   = lane >> 2;
    const int qc   = lane & 3;
    const int fr   = tid >> 2;             // 0..63
    const int fch  = (tid & 3) * 8;

    const uint32_t sbase = smem_u32(smh);

    float acc[4][4][4];
#pragma unroll
    for (int mt = 0; mt < 4; mt++)
#pragma unroll
        for (int nt = 0; nt < 4; nt++)
#pragma unroll
            for (int r = 0; r < 4; r++) acc[mt][nt][r] = 0.f;

    auto issue = [&](int it) {
        const int s    = it % NSTAGE;
        const int coef = cg * CPC + (it >> 4);
        const int ci0  = (it & 15) << 5;
        const uint32_t stA = sbase + (uint32_t)s * STAGE_B;
        const uint32_t stB = stA + TILE_H * 2;
        const __half* Ab = g_U + ((size_t)coef * C_ + oc0 + fr) * C_ + ci0 + fch;
        const __half* Bb = g_V + ((size_t)coef * NT_ + n0 + fr) * C_ + ci0 + fch;
        cp16(stA + (uint32_t)(fr * STR + fch) * 2, Ab);
        cp16(stA + (uint32_t)((fr + 64) * STR + fch) * 2, Ab + (size_t)64 * C_);
        cp16(stB + (uint32_t)(fr * STR + fch) * 2, Bb);
        cp16(stB + (uint32_t)((fr + 64) * STR + fch) * 2, Bb + (size_t)64 * C_);
        cp_commit();
    };

    issue(0);
    issue(1);

    for (int it = 0; it < NITER; it++) {
        if (it + 2 < NITER) { issue(it + 2); cp_wait<1>(); }
        else                { cp_wait<0>(); }
        __syncthreads();

        const uint32_t stA = sbase + (uint32_t)(it % NSTAGE) * STAGE_B;
        const uint32_t stB = stA + TILE_H * 2;

#pragma unroll
        for (int ks = 0; ks < 2; ks++) {
            const int k0 = ks * 16;
            uint32_t a[4][4], bf[2][4];
#pragma unroll
            for (int mt = 0; mt < 4; mt++) {
                int row  = wm * 64 + mt * 16 + (lane & 15);
                int colh = k0 + ((lane >> 4) << 3);
                ldsm4(a[mt], stA + (uint32_t)(row * STR + colh) * 2);
            }
#pragma unroll
            for (int pp = 0; pp < 2; pp++) {
                int sub  = lane >> 3;
                int n    = wn * 32 + (pp * 2 + (sub >> 1)) * 8 + (lane & 7);
                int colh = k0 + ((sub & 1) << 3);
                ldsm4(bf[pp], stB + (uint32_t)(n * STR + colh) * 2);
            }
#pragma unroll
            for (int mt = 0; mt < 4; mt++) {
#pragma unroll
                for (int nt = 0; nt < 4; nt++)
                    mma_f16(acc[mt][nt], a[mt], &bf[nt >> 1][(nt & 1) * 2]);
            }
        }
        __syncthreads();

        if ((it & 15) == 15) {
            // epilogue for this coef: store fp16 M, reset acc
            const int coef = cg * CPC + (it >> 4);
#pragma unroll
            for (int mt = 0; mt < 4; mt++) {
                const int oc_r = oc0 + wm * 64 + mt * 16 + qr;
                __half* o0 = g_M + ((size_t)coef * C_ + oc_r) * NT_ + n0 + wn * 32 + qc * 2;
                __half* o1 = o0 + (size_t)8 * NT_;
#pragma unroll
                for (int nt = 0; nt < 4; nt++) {
                    *(__half2*)(o0 + nt * 8) = __floats2half2_rn(acc[mt][nt][0], acc[mt][nt][1]);
                    *(__half2*)(o1 + nt * 8) = __floats2half2_rn(acc[mt][nt][2], acc[mt][nt][3]);
#pragma unroll
                    for (int r = 0; r < 4; r++) acc[mt][nt][r] = 0.f;
                }
            }
        }
    }
}

// ---------------- inverse transform: Y = A^T M A, demodulate, store ----------------
__global__ void __launch_bounds__(256)
wino_inv_kernel(float* __restrict__ out) {
    const int n  = blockIdx.x * 256 + threadIdx.x;   // 0..16383
    const int oc = blockIdx.y;
    const int b  = n >> 10, t = n & 1023;
    const int ty = t >> 5, tx = t & 31;

    float m[16];
#pragma unroll
    for (int c = 0; c < NCF; c++)
        m[c] = __half2float(g_M[((size_t)c * C_ + oc) * NT_ + n]);

    float z0[4], z1[4];
#pragma unroll
    for (int k = 0; k < 4; k++) {
        z0[k] = m[k * 4 + 0] + m[k * 4 + 1] + m[k * 4 + 2];
        z1[k] = m[k * 4 + 1] - m[k * 4 + 2] - m[k * 4 + 3];
    }
    const float rd = g_rdenom[b * C_ + oc];
    float y00 = (z0[0] + z0[1] + z0[2]) * rd;
    float y01 = (z1[0] + z1[1] + z1[2]) * rd;
    float y10 = (z0[1] - z0[2] - z0[3]) * rd;
    float y11 = (z1[1] - z1[2] - z1[3]) * rd;

    float* op = out + ((size_t)(b * C_ + oc)) * HW_ + (ty * 2) * W64 + tx * 2;
    *(float2*)op          = make_float2(y00, y01);
    *(float2*)(op + W64)  = make_float2(y10, y11);
}

// ---------------- launch ----------------
extern "C" void kernel_launch(void* const* d_in, const int* in_sizes, int n_in,
                              void* d_out, int out_size) {
    const float* x  = (const float*)d_in[0];   // (16,512,64,64)
    const float* w  = (const float*)d_in[1];   // (16,512)
    const float* cw = (const float*)d_in[2];   // (512,512,3,3)
    const float* lw = (const float*)d_in[3];   // (512,512)
    const float* lb = (const float*)d_in[4];   // (512,)
    float* out = (float*)d_out;                // (16,512,64,64) fp32

    cudaFuncSetAttribute(wino_gemm_kernel,
                         cudaFuncAttributeMaxDynamicSharedMemorySize, SMEM_BYTES);

    style_kernel<<<B_, C_>>>(w, lw, lb);
    s_kernel<<<C_, C_>>>(cw);
    rdenom_kernel<<<B_, C_>>>();
    wino_w_kernel<<<C_, C_>>>(cw);
    wino_x_kernel<<<dim3(32, C_ / 32, B_), 256>>>(x);
    wino_gemm_kernel<<<dim3(NT_ / 128, C_ / 128, NCF / CPC), 256, SMEM_BYTES>>>();
    wino_inv_kernel<<<dim3(NT_ / 256, C_), 256>>>(out);
}

// round 11
// speedup vs baseline: 1.5622x; 1.5622x over previous
#include <cuda_runtime.h>
#include <cuda_fp16.h>
#include <cstdint>

#define B_   16
#define C_   512
#define HW_  4096
#define W64  64
#define WD_  512
#define EPS_ 1e-6f
#define NT_  16384           // total Winograd tiles = B_ * 1024
#define NCF  16              // Winograd coefficients (4x4)

// ---------------- scratch (__device__ globals; no runtime alloc) ----------------
__device__ float  g_style[B_ * C_];
__device__ float  g_S[C_ * C_];
__device__ float  g_rdenom[B_ * C_];
__device__ __half g_U[(size_t)NCF * C_ * C_];        // (coef, oc, ic) fp16
__device__ __half g_V[(size_t)NCF * NT_ * C_];       // (coef, n, ic)  fp16
__device__ __half g_M[(size_t)NCF * C_ * NT_];       // (coef, oc, n)  fp16

// ---------------- helpers ----------------
__device__ __forceinline__ uint32_t smem_u32(const void* p) {
    uint32_t a;
    asm("{ .reg .u64 t; cvta.to.shared.u64 t, %1; cvt.u32.u64 %0, t; }" : "=r"(a) : "l"(p));
    return a;
}
__device__ __forceinline__ void cp16(uint32_t dst, const void* src) {
    asm volatile("cp.async.cg.shared.global [%0], [%1], 16;" :: "r"(dst), "l"(src));
}
template <int N>
__device__ __forceinline__ void cp_wait() {
    asm volatile("cp.async.wait_group %0;" :: "n"(N) : "memory");
}
__device__ __forceinline__ void cp_commit() {
    asm volatile("cp.async.commit_group;" ::: "memory");
}
__device__ __forceinline__ void ldsm4(uint32_t* r, uint32_t addr) {
    asm volatile("ldmatrix.sync.aligned.m8n8.x4.shared.b16 {%0,%1,%2,%3}, [%4];"
                 : "=r"(r[0]), "=r"(r[1]), "=r"(r[2]), "=r"(r[3]) : "r"(addr));
}
__device__ __forceinline__ void mma_f16(float* d, const uint32_t* a, const uint32_t* bf) {
    asm volatile(
        "mma.sync.aligned.m16n8k16.row.col.f32.f16.f16.f32 "
        "{%0,%1,%2,%3}, {%4,%5,%6,%7}, {%8,%9}, {%0,%1,%2,%3};"
        : "+f"(d[0]), "+f"(d[1]), "+f"(d[2]), "+f"(d[3])
        : "r"(a[0]), "r"(a[1]), "r"(a[2]), "r"(a[3]), "r"(bf[0]), "r"(bf[1]));
}

// ---------------- prologue: style / S / rdenom ----------------
__global__ void style_kernel(const float* __restrict__ w, const float* __restrict__ lw,
                             const float* __restrict__ lb) {
    __shared__ float ws[WD_];
    int b = blockIdx.x, o = threadIdx.x;
    ws[o] = w[b * WD_ + o];
    __syncthreads();
    const float* lwr = lw + (size_t)o * WD_;
    float acc = lb[o];
#pragma unroll 8
    for (int d = 0; d < WD_; d++) acc = fmaf(ws[d], lwr[d], acc);
    g_style[b * C_ + o] = acc;
}

__global__ void s_kernel(const float* __restrict__ cw) {
    int o = blockIdx.x, i = threadIdx.x;
    const float* p = cw + ((size_t)o * C_ + i) * 9;
    float s = 0.f;
#pragma unroll
    for (int k = 0; k < 9; k++) { float v = p[k]; s = fmaf(v, v, s); }
    g_S[o * C_ + i] = s;
}

__global__ void rdenom_kernel() {
    __shared__ float st2[C_];
    int b = blockIdx.x, o = threadIdx.x;
    float s = g_style[b * C_ + o];
    st2[o] = s * s;
    __syncthreads();
    const float* Sr = g_S + (size_t)o * C_;
    float acc = EPS_;
#pragma unroll 8
    for (int i = 0; i < C_; i++) acc = fmaf(Sr[i], st2[i], acc);
    g_rdenom[b * C_ + o] = rsqrtf(acc);
}

// ---------------- Winograd weight transform: U = G g G^T ----------------
__global__ void wino_w_kernel(const float* __restrict__ cw) {
    int o = blockIdx.x, i = threadIdx.x;
    const float* g = cw + ((size_t)o * C_ + i) * 9;
    float q[3][3];
#pragma unroll
    for (int r = 0; r < 3; r++)
#pragma unroll
        for (int c = 0; c < 3; c++) q[r][c] = g[r * 3 + c];
    float t[4][3];
#pragma unroll
    for (int c = 0; c < 3; c++) {
        t[0][c] = q[0][c];
        t[1][c] = 0.5f * (q[0][c] + q[1][c] + q[2][c]);
        t[2][c] = 0.5f * (q[0][c] - q[1][c] + q[2][c]);
        t[3][c] = q[2][c];
    }
#pragma unroll
    for (int r = 0; r < 4; r++) {
        float u0 = t[r][0];
        float u1 = 0.5f * (t[r][0] + t[r][1] + t[r][2]);
        float u2 = 0.5f * (t[r][0] - t[r][1] + t[r][2]);
        float u3 = t[r][2];
        g_U[((size_t)(r * 4 + 0) * C_ + o) * C_ + i] = __float2half_rn(u0);
        g_U[((size_t)(r * 4 + 1) * C_ + o) * C_ + i] = __float2half_rn(u1);
        g_U[((size_t)(r * 4 + 2) * C_ + o) * C_ + i] = __float2half_rn(u2);
        g_U[((size_t)(r * 4 + 3) * C_ + o) * C_ + i] = __float2half_rn(u3);
    }
}

// ---------------- Winograd input transform: V = B^T d B (style folded) ----------------
__global__ void __launch_bounds__(256)
wino_x_kernel(const float* __restrict__ x) {
    __shared__ float xs[4][32][71];
    const int b = blockIdx.z, chg = blockIdx.y * 32, ty = blockIdx.x;
    const int tid = threadIdx.x;

    for (int idx = tid; idx < 4 * 32 * 68; idx += 256) {
        int r   = idx / (32 * 68);
        int rem = idx % (32 * 68);
        int ch  = rem / 68;
        int col = rem % 68;
        if (col < 66) {
            int y  = ty * 2 - 1 + r;
            int xg = col - 1;
            float v = 0.f;
            if ((unsigned)y < W64 && (unsigned)xg < W64)
                v = x[((size_t)(b * C_ + chg + ch)) * HW_ + y * W64 + xg];
            xs[r][ch][col] = v;
        }
    }
    __syncthreads();

    const int tx  = tid >> 3;          // 0..31 tile col
    const int ch4 = (tid & 7) * 4;     // 0,4,...,28
    const int n   = b * 1024 + ty * 32 + tx;

    unsigned short hs[NCF][4];
#pragma unroll
    for (int cc = 0; cc < 4; cc++) {
        const int ch = ch4 + cc;
        const float st = g_style[b * C_ + chg + ch];
        float d[4][4];
#pragma unroll
        for (int r = 0; r < 4; r++)
#pragma unroll
            for (int c = 0; c < 4; c++) d[r][c] = xs[r][ch][2 * tx + c];
        float wv[4][4];
#pragma unroll
        for (int c = 0; c < 4; c++) {
            wv[0][c] = d[0][c] - d[2][c];
            wv[1][c] = d[1][c] + d[2][c];
            wv[2][c] = d[2][c] - d[1][c];
            wv[3][c] = d[1][c] - d[3][c];
        }
#pragma unroll
        for (int r = 0; r < 4; r++) {
            float v0 = wv[r][0] - wv[r][2];
            float v1 = wv[r][1] + wv[r][2];
            float v2 = wv[r][2] - wv[r][1];
            float v3 = wv[r][1] - wv[r][3];
            hs[r * 4 + 0][cc] = __half_as_ushort(__float2half_rn(v0 * st));
            hs[r * 4 + 1][cc] = __half_as_ushort(__float2half_rn(v1 * st));
            hs[r * 4 + 2][cc] = __half_as_ushort(__float2half_rn(v2 * st));
            hs[r * 4 + 3][cc] = __half_as_ushort(__float2half_rn(v3 * st));
        }
    }
#pragma unroll
    for (int c = 0; c < NCF; c++) {
        uint2 val;
        val.x = (uint32_t)hs[c][0] | ((uint32_t)hs[c][1] << 16);
        val.y = (uint32_t)hs[c][2] | ((uint32_t)hs[c][3] << 16);
        *(uint2*)(g_V + ((size_t)c * NT_ + n) * C_ + chg + ch4) = val;
    }
}

// ---------------- Winograd GEMM: M[coef] = U[coef] @ V[coef]^T (fp16 out) ----------------
// CTA 128 oc x 128 n; K = 512 in 8 chunks of 64 ch. 8 warps (wm2 x wn4), warp tile
// 64x32 = 4x4 m16n8k16 tiles x 4 ksteps. 3-stage cp.async ring, two syncs/iter.
// STR=72 halves (144B): 16B-aligned fills; ldsm 8-row phases hit disjoint bank groups.
#define STR    72
#define TILE_H (128 * STR)                 // 9216 halves per tile
#define STAGE_B (2 * TILE_H * 2)           // A + B per stage = 36864 bytes
#define NSTAGE 3
#define SMEM_BYTES (NSTAGE * STAGE_B)      // 110592

__global__ void __launch_bounds__(256, 2)
wino_gemm_kernel() {
    extern __shared__ __half smh[];
    const int tid  = threadIdx.x;
    const int coef = blockIdx.z;
    const int oc0  = blockIdx.y * 128;
    const int n0   = blockIdx.x * 128;
    const int lane = tid & 31;
    const int wrp  = tid >> 5;
    const int wm   = wrp & 1;
    const int wn   = wrp >> 1;
    const int qr   = lane >> 2;
    const int qc   = lane & 3;
    const int fr   = tid >> 2;             // 0..63
    const int fq   = (tid & 3) * 16;       // half offset in 64-ch chunk: 0,16,32,48

    const __half* Ag = g_U + ((size_t)coef * C_ + oc0) * C_;
    const __half* Bg = g_V + ((size_t)coef * NT_ + n0) * C_;
    const uint32_t sbase = smem_u32(smh);

    float acc[4][4][4];
#pragma unroll
    for (int mt = 0; mt < 4; mt++)
#pragma unroll
        for (int nt = 0; nt < 4; nt++)
#pragma unroll
            for (int r = 0; r < 4; r++) acc[mt][nt][r] = 0.f;

    auto issue = [&](int it) {
        const int s   = it % NSTAGE;
        const int ci0 = it << 6;
        const uint32_t stA = sbase + (uint32_t)s * STAGE_B;
        const uint32_t stB = stA + TILE_H * 2;
        const __half* Ab = Ag + (size_t)fr * C_ + ci0 + fq;
        const __half* Bb = Bg + (size_t)fr * C_ + ci0 + fq;
        cp16(stA + (uint32_t)(fr * STR + fq) * 2, Ab);
        cp16(stA + (uint32_t)(fr * STR + fq + 8) * 2, Ab + 8);
        cp16(stA + (uint32_t)((fr + 64) * STR + fq) * 2, Ab + (size_t)64 * C_);
        cp16(stA + (uint32_t)((fr + 64) * STR + fq + 8) * 2, Ab + (size_t)64 * C_ + 8);
        cp16(stB + (uint32_t)(fr * STR + fq) * 2, Bb);
        cp16(stB + (uint32_t)(fr * STR + fq + 8) * 2, Bb + 8);
        cp16(stB + (uint32_t)((fr + 64) * STR + fq) * 2, Bb + (size_t)64 * C_);
        cp16(stB + (uint32_t)((fr + 64) * STR + fq + 8) * 2, Bb + (size_t)64 * C_ + 8);
        cp_commit();
    };

    issue(0);
    issue(1);

    for (int it = 0; it < 8; it++) {
        if (it + 2 < 8) { issue(it + 2); cp_wait<1>(); }
        else            { cp_wait<0>(); }
        __syncthreads();

        const uint32_t stA = sbase + (uint32_t)(it % NSTAGE) * STAGE_B;
        const uint32_t stB = stA + TILE_H * 2;

#pragma unroll
        for (int ks = 0; ks < 4; ks++) {
            const int k0 = ks * 16;
            uint32_t a[4][4], bf[2][4];
#pragma unroll
            for (int mt = 0; mt < 4; mt++) {
                int row  = wm * 64 + mt * 16 + (lane & 15);
                int colh = k0 + ((lane >> 4) << 3);
                ldsm4(a[mt], stA + (uint32_t)(row * STR + colh) * 2);
            }
#pragma unroll
            for (int pp = 0; pp < 2; pp++) {
                int sub  = lane >> 3;
                int n    = wn * 32 + (pp * 2 + (sub >> 1)) * 8 + (lane & 7);
                int colh = k0 + ((sub & 1) << 3);
                ldsm4(bf[pp], stB + (uint32_t)(n * STR + colh) * 2);
            }
#pragma unroll
            for (int mt = 0; mt < 4; mt++) {
#pragma unroll
                for (int nt = 0; nt < 4; nt++)
                    mma_f16(acc[mt][nt], a[mt], &bf[nt >> 1][(nt & 1) * 2]);
            }
        }
        __syncthreads();
    }

    // epilogue: store M[coef][oc][n] as fp16
#pragma unroll
    for (int mt = 0; mt < 4; mt++) {
        const int oc_r = oc0 + wm * 64 + mt * 16 + qr;
        __half* o0 = g_M + ((size_t)coef * C_ + oc_r) * NT_ + n0 + wn * 32 + qc * 2;
        __half* o1 = o0 + (size_t)8 * NT_;
#pragma unroll
        for (int nt = 0; nt < 4; nt++) {
            *(__half2*)(o0 + nt * 8) = __floats2half2_rn(acc[mt][nt][0], acc[mt][nt][1]);
            *(__half2*)(o1 + nt * 8) = __floats2half2_rn(acc[mt][nt][2], acc[mt][nt][3]);
        }
    }
}

// ---------------- inverse transform: Y = A^T M A, demodulate, store ----------------
__global__ void __launch_bounds__(256)
wino_inv_kernel(float* __restrict__ out) {
    const int n  = blockIdx.x * 256 + threadIdx.x;   // 0..16383
    const int oc = blockIdx.y;
    const int b  = n >> 10, t = n & 1023;
    const int ty = t >> 5, tx = t & 31;

    float m[16];
#pragma unroll
    for (int c = 0; c < NCF; c++)
        m[c] = __half2float(g_M[((size_t)c * C_ + oc) * NT_ + n]);

    float z0[4], z1[4];
#pragma unroll
    for (int k = 0; k < 4; k++) {
        z0[k] = m[k * 4 + 0] + m[k * 4 + 1] + m[k * 4 + 2];
        z1[k] = m[k * 4 + 1] - m[k * 4 + 2] - m[k * 4 + 3];
    }
    const float rd = g_rdenom[b * C_ + oc];
    float y00 = (z0[0] + z0[1] + z0[2]) * rd;
    float y01 = (z1[0] + z1[1] + z1[2]) * rd;
    float y10 = (z0[1] - z0[2] - z0[3]) * rd;
    float y11 = (z1[1] - z1[2] - z1[3]) * rd;

    float* op = out + ((size_t)(b * C_ + oc)) * HW_ + (ty * 2) * W64 + tx * 2;
    *(float2*)op          = make_float2(y00, y01);
    *(float2*)(op + W64)  = make_float2(y10, y11);
}

// ---------------- launch ----------------
// Order chosen so the GEMM lands in the ncu capture slot (previously wino_w,
// 4th launch, was captured). Dependencies: wino_x needs style; gemm needs
// wino_w + wino_x; rdenom needs style + s; inv needs gemm + rdenom.
extern "C" void kernel_launch(void* const* d_in, const int* in_sizes, int n_in,
                              void* d_out, int out_size) {
    const float* x  = (const float*)d_in[0];   // (16,512,64,64)
    const float* w  = (const float*)d_in[1];   // (16,512)
    const float* cw = (const float*)d_in[2];   // (512,512,3,3)
    const float* lw = (const float*)d_in[3];   // (512,512)
    const float* lb = (const float*)d_in[4];   // (512,)
    float* out = (float*)d_out;                // (16,512,64,64) fp32

    cudaFuncSetAttribute(wino_gemm_kernel,
                         cudaFuncAttributeMaxDynamicSharedMemorySize, SMEM_BYTES);

    style_kernel<<<B_, C_>>>(w, lw, lb);                       // 0
    wino_w_kernel<<<C_, C_>>>(cw);                             // 1
    wino_x_kernel<<<dim3(32, C_ / 32, B_), 256>>>(x);          // 2
    wino_gemm_kernel<<<dim3(NT_ / 128, C_ / 128, NCF), 256, SMEM_BYTES>>>();  // 3 (profiled)
    s_kernel<<<C_, C_>>>(cw);                                  // 4
    rdenom_kernel<<<B_, C_>>>();                               // 5
    wino_inv_kernel<<<dim3(NT_ / 256, C_), 256>>>(out);        // 6
}

// round 12
// speedup vs baseline: 1.6085x; 1.0296x over previous
#include <cuda_runtime.h>
#include <cuda_fp16.h>
#include <cstdint>

#define B_   16
#define C_   512
#define HW_  4096
#define W64  64
#define WD_  512
#define EPS_ 1e-6f
#define NT_  16384           // total Winograd tiles = B_ * 1024
#define NCF  16              // Winograd coefficients (4x4)

// ---------------- scratch (__device__ globals; no runtime alloc) ----------------
__device__ float  g_style[B_ * C_];
__device__ float  g_S[C_ * C_];
__device__ float  g_rdenom[B_ * C_];
__device__ __half g_U[(size_t)NCF * C_ * C_];        // (coef, oc, ic) fp16
__device__ __half g_V[(size_t)NCF * NT_ * C_];       // (coef, n, ic)  fp16
__device__ __half g_M[(size_t)NCF * C_ * NT_];       // (coef, oc, n)  fp16

// ---------------- helpers ----------------
__device__ __forceinline__ uint32_t smem_u32(const void* p) {
    uint32_t a;
    asm("{ .reg .u64 t; cvta.to.shared.u64 t, %1; cvt.u32.u64 %0, t; }" : "=r"(a) : "l"(p));
    return a;
}
__device__ __forceinline__ void cp16(uint32_t dst, const void* src) {
    asm volatile("cp.async.cg.shared.global [%0], [%1], 16;" :: "r"(dst), "l"(src));
}
template <int N>
__device__ __forceinline__ void cp_wait() {
    asm volatile("cp.async.wait_group %0;" :: "n"(N) : "memory");
}
__device__ __forceinline__ void cp_commit() {
    asm volatile("cp.async.commit_group;" ::: "memory");
}
__device__ __forceinline__ void ldsm4(uint32_t* r, uint32_t addr) {
    asm volatile("ldmatrix.sync.aligned.m8n8.x4.shared.b16 {%0,%1,%2,%3}, [%4];"
                 : "=r"(r[0]), "=r"(r[1]), "=r"(r[2]), "=r"(r[3]) : "r"(addr));
}
__device__ __forceinline__ void mma_f16(float* d, const uint32_t* a, const uint32_t* bf) {
    asm volatile(
        "mma.sync.aligned.m16n8k16.row.col.f32.f16.f16.f32 "
        "{%0,%1,%2,%3}, {%4,%5,%6,%7}, {%8,%9}, {%0,%1,%2,%3};"
        : "+f"(d[0]), "+f"(d[1]), "+f"(d[2]), "+f"(d[3])
        : "r"(a[0]), "r"(a[1]), "r"(a[2]), "r"(a[3]), "r"(bf[0]), "r"(bf[1]));
}

// ---------------- prologue: style / rdenom ----------------
__global__ void style_kernel(const float* __restrict__ w, const float* __restrict__ lw,
                             const float* __restrict__ lb) {
    __shared__ float ws[WD_];
    int b = blockIdx.x, o = threadIdx.x;
    ws[o] = w[b * WD_ + o];
    __syncthreads();
    const float* lwr = lw + (size_t)o * WD_;
    float acc = lb[o];
#pragma unroll 8
    for (int d = 0; d < WD_; d++) acc = fmaf(ws[d], lwr[d], acc);
    g_style[b * C_ + o] = acc;
}

__global__ void rdenom_kernel() {
    __shared__ float st2[C_];
    int b = blockIdx.x, o = threadIdx.x;
    float s = g_style[b * C_ + o];
    st2[o] = s * s;
    __syncthreads();
    const float* Sr = g_S + (size_t)o * C_;
    float acc = EPS_;
#pragma unroll 8
    for (int i = 0; i < C_; i++) acc = fmaf(Sr[i], st2[i], acc);
    g_rdenom[b * C_ + o] = rsqrtf(acc);
}

// ---------------- Winograd weight transform + S: U = G g G^T; S = sum g^2 ----------------
__global__ void wino_w_kernel(const float* __restrict__ cw) {
    int o = blockIdx.x, i = threadIdx.x;
    const float* g = cw + ((size_t)o * C_ + i) * 9;
    float q[3][3];
    float s = 0.f;
#pragma unroll
    for (int r = 0; r < 3; r++)
#pragma unroll
        for (int c = 0; c < 3; c++) { q[r][c] = g[r * 3 + c]; s = fmaf(q[r][c], q[r][c], s); }
    g_S[o * C_ + i] = s;
    float t[4][3];
#pragma unroll
    for (int c = 0; c < 3; c++) {
        t[0][c] = q[0][c];
        t[1][c] = 0.5f * (q[0][c] + q[1][c] + q[2][c]);
        t[2][c] = 0.5f * (q[0][c] - q[1][c] + q[2][c]);
        t[3][c] = q[2][c];
    }
#pragma unroll
    for (int r = 0; r < 4; r++) {
        float u0 = t[r][0];
        float u1 = 0.5f * (t[r][0] + t[r][1] + t[r][2]);
        float u2 = 0.5f * (t[r][0] - t[r][1] + t[r][2]);
        float u3 = t[r][2];
        g_U[((size_t)(r * 4 + 0) * C_ + o) * C_ + i] = __float2half_rn(u0);
        g_U[((size_t)(r * 4 + 1) * C_ + o) * C_ + i] = __float2half_rn(u1);
        g_U[((size_t)(r * 4 + 2) * C_ + o) * C_ + i] = __float2half_rn(u2);
        g_U[((size_t)(r * 4 + 3) * C_ + o) * C_ + i] = __float2half_rn(u3);
    }
}

// ---------------- Winograd input transform: V = B^T d B (style folded) ----------------
__global__ void __launch_bounds__(256)
wino_x_kernel(const float* __restrict__ x) {
    __shared__ float xs[4][32][71];
    const int b = blockIdx.z, chg = blockIdx.y * 32, ty = blockIdx.x;
    const int tid = threadIdx.x;

    for (int idx = tid; idx < 4 * 32 * 68; idx += 256) {
        int r   = idx / (32 * 68);
        int rem = idx % (32 * 68);
        int ch  = rem / 68;
        int col = rem % 68;
        if (col < 66) {
            int y  = ty * 2 - 1 + r;
            int xg = col - 1;
            float v = 0.f;
            if ((unsigned)y < W64 && (unsigned)xg < W64)
                v = x[((size_t)(b * C_ + chg + ch)) * HW_ + y * W64 + xg];
            xs[r][ch][col] = v;
        }
    }
    __syncthreads();

    const int tx  = tid >> 3;          // 0..31 tile col
    const int ch4 = (tid & 7) * 4;     // 0,4,...,28
    const int n   = b * 1024 + ty * 32 + tx;

    unsigned short hs[NCF][4];
#pragma unroll
    for (int cc = 0; cc < 4; cc++) {
        const int ch = ch4 + cc;
        const float st = g_style[b * C_ + chg + ch];
        float d[4][4];
#pragma unroll
        for (int r = 0; r < 4; r++)
#pragma unroll
            for (int c = 0; c < 4; c++) d[r][c] = xs[r][ch][2 * tx + c];
        float wv[4][4];
#pragma unroll
        for (int c = 0; c < 4; c++) {
            wv[0][c] = d[0][c] - d[2][c];
            wv[1][c] = d[1][c] + d[2][c];
            wv[2][c] = d[2][c] - d[1][c];
            wv[3][c] = d[1][c] - d[3][c];
        }
#pragma unroll
        for (int r = 0; r < 4; r++) {
            float v0 = wv[r][0] - wv[r][2];
            float v1 = wv[r][1] + wv[r][2];
            float v2 = wv[r][2] - wv[r][1];
            float v3 = wv[r][1] - wv[r][3];
            hs[r * 4 + 0][cc] = __half_as_ushort(__float2half_rn(v0 * st));
            hs[r * 4 + 1][cc] = __half_as_ushort(__float2half_rn(v1 * st));
            hs[r * 4 + 2][cc] = __half_as_ushort(__float2half_rn(v2 * st));
            hs[r * 4 + 3][cc] = __half_as_ushort(__float2half_rn(v3 * st));
        }
    }
#pragma unroll
    for (int c = 0; c < NCF; c++) {
        uint2 val;
        val.x = (uint32_t)hs[c][0] | ((uint32_t)hs[c][1] << 16);
        val.y = (uint32_t)hs[c][2] | ((uint32_t)hs[c][3] << 16);
        *(uint2*)(g_V + ((size_t)c * NT_ + n) * C_ + chg + ch4) = val;
    }
}

// ---------------- Winograd GEMM: M[coef] = U[coef] @ V[coef]^T (fp16 out) ----------------
// CTA 128 oc x 128 n; K = 512 in 8 chunks of 64 ch. 8 warps (wm2 x wn4), warp tile
// 64x32 = 4x4 m16n8k16 tiles x 4 ksteps. 3-stage cp.async ring, two syncs/iter.
#define STR    72
#define TILE_H (128 * STR)                 // 9216 halves per tile
#define STAGE_B (2 * TILE_H * 2)           // A + B per stage = 36864 bytes
#define NSTAGE 3
#define SMEM_BYTES (NSTAGE * STAGE_B)      // 110592

__global__ void __launch_bounds__(256, 2)
wino_gemm_kernel() {
    extern __shared__ __half smh[];
    const int tid  = threadIdx.x;
    const int coef = blockIdx.z;
    const int oc0  = blockIdx.y * 128;
    const int n0   = blockIdx.x * 128;
    const int lane = tid & 31;
    const int wrp  = tid >> 5;
    const int wm   = wrp & 1;
    const int wn   = wrp >> 1;
    const int qr   = lane >> 2;
    const int qc   = lane & 3;
    const int fr   = tid >> 2;             // 0..63
    const int fq   = (tid & 3) * 16;       // half offset in 64-ch chunk

    const __half* Ag = g_U + ((size_t)coef * C_ + oc0) * C_;
    const __half* Bg = g_V + ((size_t)coef * NT_ + n0) * C_;
    const uint32_t sbase = smem_u32(smh);

    float acc[4][4][4];
#pragma unroll
    for (int mt = 0; mt < 4; mt++)
#pragma unroll
        for (int nt = 0; nt < 4; nt++)
#pragma unroll
            for (int r = 0; r < 4; r++) acc[mt][nt][r] = 0.f;

    auto issue = [&](int it) {
        const int s   = it % NSTAGE;
        const int ci0 = it << 6;
        const uint32_t stA = sbase + (uint32_t)s * STAGE_B;
        const uint32_t stB = stA + TILE_H * 2;
        const __half* Ab = Ag + (size_t)fr * C_ + ci0 + fq;
        const __half* Bb = Bg + (size_t)fr * C_ + ci0 + fq;
        cp16(stA + (uint32_t)(fr * STR + fq) * 2, Ab);
        cp16(stA + (uint32_t)(fr * STR + fq + 8) * 2, Ab + 8);
        cp16(stA + (uint32_t)((fr + 64) * STR + fq) * 2, Ab + (size_t)64 * C_);
        cp16(stA + (uint32_t)((fr + 64) * STR + fq + 8) * 2, Ab + (size_t)64 * C_ + 8);
        cp16(stB + (uint32_t)(fr * STR + fq) * 2, Bb);
        cp16(stB + (uint32_t)(fr * STR + fq + 8) * 2, Bb + 8);
        cp16(stB + (uint32_t)((fr + 64) * STR + fq) * 2, Bb + (size_t)64 * C_);
        cp16(stB + (uint32_t)((fr + 64) * STR + fq + 8) * 2, Bb + (size_t)64 * C_ + 8);
        cp_commit();
    };

    issue(0);
    issue(1);

    for (int it = 0; it < 8; it++) {
        if (it + 2 < 8) { issue(it + 2); cp_wait<1>(); }
        else            { cp_wait<0>(); }
        __syncthreads();

        const uint32_t stA = sbase + (uint32_t)(it % NSTAGE) * STAGE_B;
        const uint32_t stB = stA + TILE_H * 2;

#pragma unroll
        for (int ks = 0; ks < 4; ks++) {
            const int k0 = ks * 16;
            uint32_t a[4][4], bf[2][4];
#pragma unroll
            for (int mt = 0; mt < 4; mt++) {
                int row  = wm * 64 + mt * 16 + (lane & 15);
                int colh = k0 + ((lane >> 4) << 3);
                ldsm4(a[mt], stA + (uint32_t)(row * STR + colh) * 2);
            }
#pragma unroll
            for (int pp = 0; pp < 2; pp++) {
                int sub  = lane >> 3;
                int n    = wn * 32 + (pp * 2 + (sub >> 1)) * 8 + (lane & 7);
                int colh = k0 + ((sub & 1) << 3);
                ldsm4(bf[pp], stB + (uint32_t)(n * STR + colh) * 2);
            }
#pragma unroll
            for (int mt = 0; mt < 4; mt++) {
#pragma unroll
                for (int nt = 0; nt < 4; nt++)
                    mma_f16(acc[mt][nt], a[mt], &bf[nt >> 1][(nt & 1) * 2]);
            }
        }
        __syncthreads();
    }

    // epilogue: store M[coef][oc][n] as fp16
#pragma unroll
    for (int mt = 0; mt < 4; mt++) {
        const int oc_r = oc0 + wm * 64 + mt * 16 + qr;
        __half* o0 = g_M + ((size_t)coef * C_ + oc_r) * NT_ + n0 + wn * 32 + qc * 2;
        __half* o1 = o0 + (size_t)8 * NT_;
#pragma unroll
        for (int nt = 0; nt < 4; nt++) {
            *(__half2*)(o0 + nt * 8) = __floats2half2_rn(acc[mt][nt][0], acc[mt][nt][1]);
            *(__half2*)(o1 + nt * 8) = __floats2half2_rn(acc[mt][nt][2], acc[mt][nt][3]);
        }
    }
}

// ---------------- inverse transform: Y = A^T M A, demodulate, store ----------------
// Thread handles a PAIR of adjacent tiles: half2 loads per M plane, float4 stores.
__global__ void __launch_bounds__(256)
wino_inv_kernel(float* __restrict__ out) {
    const int np = blockIdx.x * 256 + threadIdx.x;   // 0..8191 tile pairs
    const int n  = np * 2;
    const int oc = blockIdx.y;
    const int b  = n >> 10, t = n & 1023;
    const int ty = t >> 5, tx = t & 31;              // tx even; tiles tx, tx+1

    float mx[16], my[16];
#pragma unroll
    for (int c = 0; c < NCF; c++) {
        __half2 h = *(const __half2*)(g_M + ((size_t)c * C_ + oc) * NT_ + n);
        float2 f = __half22float2(h);
        mx[c] = f.x; my[c] = f.y;
    }

    const float rd = g_rdenom[b * C_ + oc];
    float z0x[4], z1x[4], z0y[4], z1y[4];
#pragma unroll
    for (int k = 0; k < 4; k++) {
        z0x[k] = mx[k * 4 + 0] + mx[k * 4 + 1] + mx[k * 4 + 2];
        z1x[k] = mx[k * 4 + 1] - mx[k * 4 + 2] - mx[k * 4 + 3];
        z0y[k] = my[k * 4 + 0] + my[k * 4 + 1] + my[k * 4 + 2];
        z1y[k] = my[k * 4 + 1] - my[k * 4 + 2] - my[k * 4 + 3];
    }
    float* op = out + ((size_t)(b * C_ + oc)) * HW_ + (ty * 2) * W64 + tx * 2;
    *(float4*)op = make_float4((z0x[0] + z0x[1] + z0x[2]) * rd,
                               (z1x[0] + z1x[1] + z1x[2]) * rd,
                               (z0y[0] + z0y[1] + z0y[2]) * rd,
                               (z1y[0] + z1y[1] + z1y[2]) * rd);
    *(float4*)(op + W64) = make_float4((z0x[1] - z0x[2] - z0x[3]) * rd,
                                       (z1x[1] - z1x[2] - z1x[3]) * rd,
                                       (z0y[1] - z0y[2] - z0y[3]) * rd,
                                       (z1y[1] - z1y[2] - z1y[3]) * rd);
}

// ---------------- launch ----------------
// Profiled slot = launch index 3 -> wino_x this round.
extern "C" void kernel_launch(void* const* d_in, const int* in_sizes, int n_in,
                              void* d_out, int out_size) {
    const float* x  = (const float*)d_in[0];   // (16,512,64,64)
    const float* w  = (const float*)d_in[1];   // (16,512)
    const float* cw = (const float*)d_in[2];   // (512,512,3,3)
    const float* lw = (const float*)d_in[3];   // (512,512)
    const float* lb = (const float*)d_in[4];   // (512,)
    float* out = (float*)d_out;                // (16,512,64,64) fp32

    cudaFuncSetAttribute(wino_gemm_kernel,
                         cudaFuncAttributeMaxDynamicSharedMemorySize, SMEM_BYTES);

    style_kernel<<<B_, C_>>>(w, lw, lb);                       // 0
    wino_w_kernel<<<C_, C_>>>(cw);                             // 1 (U + S)
    rdenom_kernel<<<B_, C_>>>();                               // 2
    wino_x_kernel<<<dim3(32, C_ / 32, B_), 256>>>(x);          // 3 (profiled)
    wino_gemm_kernel<<<dim3(NT_ / 128, C_ / 128, NCF), 256, SMEM_BYTES>>>();  // 4
    wino_inv_kernel<<<dim3(NT_ / 512, C_), 256>>>(out);        // 5
}

// round 13
// speedup vs baseline: 1.9349x; 1.2029x over previous
#include <cuda_runtime.h>
#include <cuda_fp16.h>
#include <cstdint>

#define B_   16
#define C_   512
#define HW_  4096
#define W64  64
#define WD_  512
#define EPS_ 1e-6f
#define NT_  16384           // total Winograd tiles = B_ * 1024
#define NCF  16              // Winograd coefficients (4x4)

// ---------------- scratch (__device__ globals; no runtime alloc) ----------------
__device__ float  g_style[B_ * C_];
__device__ float  g_S[C_ * C_];
__device__ float  g_rdenom[B_ * C_];
__device__ __half g_U[(size_t)NCF * C_ * C_];        // (coef, oc, ic) fp16
__device__ __half g_V[(size_t)NCF * NT_ * C_];       // (coef, n, ic)  fp16
__device__ __half g_M[(size_t)NCF * C_ * NT_];       // (coef, oc, n)  fp16

// ---------------- helpers ----------------
__device__ __forceinline__ uint32_t smem_u32(const void* p) {
    uint32_t a;
    asm("{ .reg .u64 t; cvta.to.shared.u64 t, %1; cvt.u32.u64 %0, t; }" : "=r"(a) : "l"(p));
    return a;
}
__device__ __forceinline__ void cp16(uint32_t dst, const void* src) {
    asm volatile("cp.async.cg.shared.global [%0], [%1], 16;" :: "r"(dst), "l"(src));
}
template <int N>
__device__ __forceinline__ void cp_wait() {
    asm volatile("cp.async.wait_group %0;" :: "n"(N) : "memory");
}
__device__ __forceinline__ void cp_commit() {
    asm volatile("cp.async.commit_group;" ::: "memory");
}
__device__ __forceinline__ void ldsm4(uint32_t* r, uint32_t addr) {
    asm volatile("ldmatrix.sync.aligned.m8n8.x4.shared.b16 {%0,%1,%2,%3}, [%4];"
                 : "=r"(r[0]), "=r"(r[1]), "=r"(r[2]), "=r"(r[3]) : "r"(addr));
}
__device__ __forceinline__ void mma_f16(float* d, const uint32_t* a, const uint32_t* bf) {
    asm volatile(
        "mma.sync.aligned.m16n8k16.row.col.f32.f16.f16.f32 "
        "{%0,%1,%2,%3}, {%4,%5,%6,%7}, {%8,%9}, {%0,%1,%2,%3};"
        : "+f"(d[0]), "+f"(d[1]), "+f"(d[2]), "+f"(d[3])
        : "r"(a[0]), "r"(a[1]), "r"(a[2]), "r"(a[3]), "r"(bf[0]), "r"(bf[1]));
}

// ---------------- prologue: style / rdenom ----------------
__global__ void style_kernel(const float* __restrict__ w, const float* __restrict__ lw,
                             const float* __restrict__ lb) {
    __shared__ float ws[WD_];
    int b = blockIdx.x, o = threadIdx.x;
    ws[o] = w[b * WD_ + o];
    __syncthreads();
    const float* lwr = lw + (size_t)o * WD_;
    float acc = lb[o];
#pragma unroll 8
    for (int d = 0; d < WD_; d++) acc = fmaf(ws[d], lwr[d], acc);
    g_style[b * C_ + o] = acc;
}

__global__ void rdenom_kernel() {
    __shared__ float st2[C_];
    int b = blockIdx.x, o = threadIdx.x;
    float s = g_style[b * C_ + o];
    st2[o] = s * s;
    __syncthreads();
    const float* Sr = g_S + (size_t)o * C_;
    float acc = EPS_;
#pragma unroll 8
    for (int i = 0; i < C_; i++) acc = fmaf(Sr[i], st2[i], acc);
    g_rdenom[b * C_ + o] = rsqrtf(acc);
}

// ---------------- Winograd weight transform + S: U = G g G^T; S = sum g^2 ----------------
__global__ void wino_w_kernel(const float* __restrict__ cw) {
    int o = blockIdx.x, i = threadIdx.x;
    const float* g = cw + ((size_t)o * C_ + i) * 9;
    float q[3][3];
    float s = 0.f;
#pragma unroll
    for (int r = 0; r < 3; r++)
#pragma unroll
        for (int c = 0; c < 3; c++) { q[r][c] = g[r * 3 + c]; s = fmaf(q[r][c], q[r][c], s); }
    g_S[o * C_ + i] = s;
    float t[4][3];
#pragma unroll
    for (int c = 0; c < 3; c++) {
        t[0][c] = q[0][c];
        t[1][c] = 0.5f * (q[0][c] + q[1][c] + q[2][c]);
        t[2][c] = 0.5f * (q[0][c] - q[1][c] + q[2][c]);
        t[3][c] = q[2][c];
    }
    __half* up = g_U + (size_t)o * C_ + i;
    const size_t ustr = (size_t)C_ * C_;
#pragma unroll
    for (int r = 0; r < 4; r++) {
        float u0 = t[r][0];
        float u1 = 0.5f * (t[r][0] + t[r][1] + t[r][2]);
        float u2 = 0.5f * (t[r][0] - t[r][1] + t[r][2]);
        float u3 = t[r][2];
        up[0]        = __float2half_rn(u0);
        up[ustr]     = __float2half_rn(u1);
        up[2 * ustr] = __float2half_rn(u2);
        up[3 * ustr] = __float2half_rn(u3);
        up += 4 * ustr;
    }
}

// ---------------- Winograd input transform: V = B^T d B (style folded) ----------------
// Halo fill with shift-only indexing (col fixed per thread -> hoisted bounds,
// coalesced rows); V stores via incremented plane pointer (no 64-bit mults).
__global__ void __launch_bounds__(256)
wino_x_kernel(const float* __restrict__ x) {
    __shared__ float xs[4][32][71];
    const int b = blockIdx.z, chg = blockIdx.y * 32, ty = blockIdx.x;
    const int tid = threadIdx.x;
    const float* xb = x + ((size_t)(b * C_ + chg)) * HW_;
    const int y0 = ty * 2 - 1;

    {   // main: cols 0..63 (gx = col-1): per-thread col/gx constant
        const int col = tid & 63;
        const int gx  = col - 1;
        const bool gxok = (unsigned)gx < W64;
        const int chb = tid >> 6;          // 0..3
#pragma unroll
        for (int j = 0; j < 8; j++) {      // ch = chb + j*4, r = 0..3
            int u  = chb + j * 4;          // 0..31 combined (ch, r) walker
            // iterate (r, ch): u2 = tid>>6 + j*4 spans 32 values; map r = ?, need 4*32
            ;
        }
        // (r, ch) enumeration: 128 pairs, 4 per thread-group of 64
#pragma unroll
        for (int j = 0; j < 32; j++) {
            int u  = (tid >> 6) + j * 4;   // 0..127
            int ch = u & 31;
            int r  = u >> 5;
            int y  = y0 + r;
            float v = 0.f;
            if (gxok && (unsigned)y < W64)
                v = xb[(size_t)ch * HW_ + y * W64 + gx];
            xs[r][ch][col] = v;
        }
    }
    {   // residue: cols 64,65 (gx 63,64)
        int c2 = tid & 1;
        int ch = (tid >> 1) & 31;
        int r  = tid >> 6;
        int y  = y0 + r;
        int gx = 63 + c2;
        float v = 0.f;
        if ((unsigned)y < W64 && (unsigned)gx < W64)
            v = xb[(size_t)ch * HW_ + y * W64 + gx];
        xs[r][ch][64 + c2] = v;
    }
    __syncthreads();

    const int tx  = tid >> 3;          // 0..31 tile col
    const int ch4 = (tid & 7) * 4;     // 0,4,...,28
    const int n   = b * 1024 + ty * 32 + tx;

    unsigned short hs[NCF][4];
#pragma unroll
    for (int cc = 0; cc < 4; cc++) {
        const int ch = ch4 + cc;
        const float st = g_style[b * C_ + chg + ch];
        float d[4][4];
#pragma unroll
        for (int r = 0; r < 4; r++)
#pragma unroll
            for (int c = 0; c < 4; c++) d[r][c] = xs[r][ch][2 * tx + c];
        float wv[4][4];
#pragma unroll
        for (int c = 0; c < 4; c++) {
            wv[0][c] = d[0][c] - d[2][c];
            wv[1][c] = d[1][c] + d[2][c];
            wv[2][c] = d[2][c] - d[1][c];
            wv[3][c] = d[1][c] - d[3][c];
        }
#pragma unroll
        for (int r = 0; r < 4; r++) {
            float v0 = wv[r][0] - wv[r][2];
            float v1 = wv[r][1] + wv[r][2];
            float v2 = wv[r][2] - wv[r][1];
            float v3 = wv[r][1] - wv[r][3];
            hs[r * 4 + 0][cc] = __half_as_ushort(__float2half_rn(v0 * st));
            hs[r * 4 + 1][cc] = __half_as_ushort(__float2half_rn(v1 * st));
            hs[r * 4 + 2][cc] = __half_as_ushort(__float2half_rn(v2 * st));
            hs[r * 4 + 3][cc] = __half_as_ushort(__float2half_rn(v3 * st));
        }
    }
    __half* vp = g_V + (size_t)n * C_ + chg + ch4;
    const size_t pstr = (size_t)NT_ * C_;
#pragma unroll
    for (int c = 0; c < NCF; c++) {
        uint2 val;
        val.x = (uint32_t)hs[c][0] | ((uint32_t)hs[c][1] << 16);
        val.y = (uint32_t)hs[c][2] | ((uint32_t)hs[c][3] << 16);
        *(uint2*)vp = val;
        vp += pstr;
    }
}

// ---------------- Winograd GEMM: M[coef] = U[coef] @ V[coef]^T (fp16 out) ----------------
#define STR    72
#define TILE_H (128 * STR)                 // 9216 halves per tile
#define STAGE_B (2 * TILE_H * 2)           // A + B per stage = 36864 bytes
#define NSTAGE 3
#define SMEM_BYTES (NSTAGE * STAGE_B)      // 110592

__global__ void __launch_bounds__(256, 2)
wino_gemm_kernel() {
    extern __shared__ __half smh[];
    const int tid  = threadIdx.x;
    const int coef = blockIdx.z;
    const int oc0  = blockIdx.y * 128;
    const int n0   = blockIdx.x * 128;
    const int lane = tid & 31;
    const int wrp  = tid >> 5;
    const int wm   = wrp & 1;
    const int wn   = wrp >> 1;
    const int qr   = lane >> 2;
    const int qc   = lane & 3;
    const int fr   = tid >> 2;             // 0..63
    const int fq   = (tid & 3) * 16;       // half offset in 64-ch chunk

    const __half* Ag = g_U + ((size_t)coef * C_ + oc0) * C_;
    const __half* Bg = g_V + ((size_t)coef * NT_ + n0) * C_;
    const uint32_t sbase = smem_u32(smh);

    float acc[4][4][4];
#pragma unroll
    for (int mt = 0; mt < 4; mt++)
#pragma unroll
        for (int nt = 0; nt < 4; nt++)
#pragma unroll
            for (int r = 0; r < 4; r++) acc[mt][nt][r] = 0.f;

    auto issue = [&](int it) {
        const int s   = it % NSTAGE;
        const int ci0 = it << 6;
        const uint32_t stA = sbase + (uint32_t)s * STAGE_B;
        const uint32_t stB = stA + TILE_H * 2;
        const __half* Ab = Ag + (size_t)fr * C_ + ci0 + fq;
        const __half* Bb = Bg + (size_t)fr * C_ + ci0 + fq;
        cp16(stA + (uint32_t)(fr * STR + fq) * 2, Ab);
        cp16(stA + (uint32_t)(fr * STR + fq + 8) * 2, Ab + 8);
        cp16(stA + (uint32_t)((fr + 64) * STR + fq) * 2, Ab + (size_t)64 * C_);
        cp16(stA + (uint32_t)((fr + 64) * STR + fq + 8) * 2, Ab + (size_t)64 * C_ + 8);
        cp16(stB + (uint32_t)(fr * STR + fq) * 2, Bb);
        cp16(stB + (uint32_t)(fr * STR + fq + 8) * 2, Bb + 8);
        cp16(stB + (uint32_t)((fr + 64) * STR + fq) * 2, Bb + (size_t)64 * C_);
        cp16(stB + (uint32_t)((fr + 64) * STR + fq + 8) * 2, Bb + (size_t)64 * C_ + 8);
        cp_commit();
    };

    issue(0);
    issue(1);

    for (int it = 0; it < 8; it++) {
        if (it + 2 < 8) { issue(it + 2); cp_wait<1>(); }
        else            { cp_wait<0>(); }
        __syncthreads();

        const uint32_t stA = sbase + (uint32_t)(it % NSTAGE) * STAGE_B;
        const uint32_t stB = stA + TILE_H * 2;

#pragma unroll
        for (int ks = 0; ks < 4; ks++) {
            const int k0 = ks * 16;
            uint32_t a[4][4], bf[2][4];
#pragma unroll
            for (int mt = 0; mt < 4; mt++) {
                int row  = wm * 64 + mt * 16 + (lane & 15);
                int colh = k0 + ((lane >> 4) << 3);
                ldsm4(a[mt], stA + (uint32_t)(row * STR + colh) * 2);
            }
#pragma unroll
            for (int pp = 0; pp < 2; pp++) {
                int sub  = lane >> 3;
                int n    = wn * 32 + (pp * 2 + (sub >> 1)) * 8 + (lane & 7);
                int colh = k0 + ((sub & 1) << 3);
                ldsm4(bf[pp], stB + (uint32_t)(n * STR + colh) * 2);
            }
#pragma unroll
            for (int mt = 0; mt < 4; mt++) {
#pragma unroll
                for (int nt = 0; nt < 4; nt++)
                    mma_f16(acc[mt][nt], a[mt], &bf[nt >> 1][(nt & 1) * 2]);
            }
        }
        __syncthreads();
    }

    // epilogue: store M[coef][oc][n] as fp16
#pragma unroll
    for (int mt = 0; mt < 4; mt++) {
        const int oc_r = oc0 + wm * 64 + mt * 16 + qr;
        __half* o0 = g_M + ((size_t)coef * C_ + oc_r) * NT_ + n0 + wn * 32 + qc * 2;
        __half* o1 = o0 + (size_t)8 * NT_;
#pragma unroll
        for (int nt = 0; nt < 4; nt++) {
            *(__half2*)(o0 + nt * 8) = __floats2half2_rn(acc[mt][nt][0], acc[mt][nt][1]);
            *(__half2*)(o1 + nt * 8) = __floats2half2_rn(acc[mt][nt][2], acc[mt][nt][3]);
        }
    }
}

// ---------------- inverse transform: Y = A^T M A, demodulate, store ----------------
// Thread handles FOUR adjacent tiles: one 8B load per M plane (incremented
// pointer), float4 output stores (8 consecutive pixels per row).
__global__ void __launch_bounds__(256)
wino_inv_kernel(float* __restrict__ out) {
    const int idx = blockIdx.x * 256 + threadIdx.x;  // 0..4095 quad-tiles
    const int oc  = blockIdx.y;
    const int n   = idx * 4;
    const int b   = n >> 10, t = n & 1023;
    const int ty  = t >> 5, tx = t & 31;             // tx multiple of 4

    float m[4][16];
    const __half* mp = g_M + (size_t)oc * NT_ + n;
    const size_t pstr = (size_t)C_ * NT_;
#pragma unroll
    for (int c = 0; c < NCF; c++) {
        uint2 raw = *(const uint2*)mp;
        __half2 h0 = *reinterpret_cast<__half2*>(&raw.x);
        __half2 h1 = *reinterpret_cast<__half2*>(&raw.y);
        float2 f0 = __half22float2(h0), f1 = __half22float2(h1);
        m[0][c] = f0.x; m[1][c] = f0.y; m[2][c] = f1.x; m[3][c] = f1.y;
        mp += pstr;
    }

    const float rd = g_rdenom[b * C_ + oc];
    float r0[8], r1[8];
#pragma unroll
    for (int j = 0; j < 4; j++) {
        float z0[4], z1[4];
#pragma unroll
        for (int k = 0; k < 4; k++) {
            z0[k] = m[j][k * 4 + 0] + m[j][k * 4 + 1] + m[j][k * 4 + 2];
            z1[k] = m[j][k * 4 + 1] - m[j][k * 4 + 2] - m[j][k * 4 + 3];
        }
        r0[2 * j + 0] = (z0[0] + z0[1] + z0[2]) * rd;
        r0[2 * j + 1] = (z1[0] + z1[1] + z1[2]) * rd;
        r1[2 * j + 0] = (z0[1] - z0[2] - z0[3]) * rd;
        r1[2 * j + 1] = (z1[1] - z1[2] - z1[3]) * rd;
    }
    float* op = out + ((size_t)(b * C_ + oc)) * HW_ + (ty * 2) * W64 + tx * 2;
    *(float4*)op            = make_float4(r0[0], r0[1], r0[2], r0[3]);
    *(float4*)(op + 4)      = make_float4(r0[4], r0[5], r0[6], r0[7]);
    *(float4*)(op + W64)    = make_float4(r1[0], r1[1], r1[2], r1[3]);
    *(float4*)(op + W64 + 4) = make_float4(r1[4], r1[5], r1[6], r1[7]);
}

// ---------------- launch ----------------
// Profiled slot = launch index 3 -> wino_x (verify the ALU fix).
extern "C" void kernel_launch(void* const* d_in, const int* in_sizes, int n_in,
                              void* d_out, int out_size) {
    const float* x  = (const float*)d_in[0];   // (16,512,64,64)
    const float* w  = (const float*)d_in[1];   // (16,512)
    const float* cw = (const float*)d_in[2];   // (512,512,3,3)
    const float* lw = (const float*)d_in[3];   // (512,512)
    const float* lb = (const float*)d_in[4];   // (512,)
    float* out = (float*)d_out;                // (16,512,64,64) fp32

    cudaFuncSetAttribute(wino_gemm_kernel,
                         cudaFuncAttributeMaxDynamicSharedMemorySize, SMEM_BYTES);

    style_kernel<<<B_, C_>>>(w, lw, lb);                       // 0
    wino_w_kernel<<<C_, C_>>>(cw);                             // 1 (U + S)
    rdenom_kernel<<<B_, C_>>>();                               // 2
    wino_x_kernel<<<dim3(32, C_ / 32, B_), 256>>>(x);          // 3 (profiled)
    wino_gemm_kernel<<<dim3(NT_ / 128, C_ / 128, NCF), 256, SMEM_BYTES>>>();  // 4
    wino_inv_kernel<<<dim3(NT_ / 1024, C_), 256>>>(out);       // 5
}

// round 14
// speedup vs baseline: 2.8245x; 1.4598x over previous
#include <cuda_runtime.h>
#include <cuda_fp16.h>
#include <cstdint>

#define B_   16
#define C_   512
#define HW_  4096
#define W64  64
#define WD_  512
#define EPS_ 1e-6f
#define NT_  16384           // total Winograd tiles = B_ * 1024
#define NCF  16              // Winograd coefficients (4x4)

// ---------------- scratch (__device__ globals; no runtime alloc) ----------------
__device__ float  g_style[B_ * C_];
__device__ float  g_S[C_ * C_];
__device__ __half g_U[(size_t)NCF * C_ * C_];        // (coef, oc, ic) fp16
__device__ __half g_V[(size_t)NCF * NT_ * C_];       // (coef, n, ic)  fp16
__device__ __half g_M[(size_t)C_ * NCF * NT_];       // (oc, coef, n)  fp16

// ---------------- helpers ----------------
__device__ __forceinline__ uint32_t smem_u32(const void* p) {
    uint32_t a;
    asm("{ .reg .u64 t; cvta.to.shared.u64 t, %1; cvt.u32.u64 %0, t; }" : "=r"(a) : "l"(p));
    return a;
}
__device__ __forceinline__ void cp16(uint32_t dst, const void* src) {
    asm volatile("cp.async.cg.shared.global [%0], [%1], 16;" :: "r"(dst), "l"(src));
}
template <int N>
__device__ __forceinline__ void cp_wait() {
    asm volatile("cp.async.wait_group %0;" :: "n"(N) : "memory");
}
__device__ __forceinline__ void cp_commit() {
    asm volatile("cp.async.commit_group;" ::: "memory");
}
__device__ __forceinline__ void ldsm4(uint32_t* r, uint32_t addr) {
    asm volatile("ldmatrix.sync.aligned.m8n8.x4.shared.b16 {%0,%1,%2,%3}, [%4];"
                 : "=r"(r[0]), "=r"(r[1]), "=r"(r[2]), "=r"(r[3]) : "r"(addr));
}
__device__ __forceinline__ void mma_f16(float* d, const uint32_t* a, const uint32_t* bf) {
    asm volatile(
        "mma.sync.aligned.m16n8k16.row.col.f32.f16.f16.f32 "
        "{%0,%1,%2,%3}, {%4,%5,%6,%7}, {%8,%9}, {%0,%1,%2,%3};"
        : "+f"(d[0]), "+f"(d[1]), "+f"(d[2]), "+f"(d[3])
        : "r"(a[0]), "r"(a[1]), "r"(a[2]), "r"(a[3]), "r"(bf[0]), "r"(bf[1]));
}

// ---------------- Winograd weight transform + S + style ----------------
// Block o (512 threads = ic): U = G g G^T (fp16), S[o,i] = sum g^2,
// style[b,o] = dot(w[b,:], lw[o,:]) + lb[o] via block reduction.
__global__ void __launch_bounds__(512)
wino_w_kernel(const float* __restrict__ cw, const float* __restrict__ w,
              const float* __restrict__ lw, const float* __restrict__ lb) {
    __shared__ float red[16][17];          // [warp][b]
    const int o = blockIdx.x, i = threadIdx.x;

    // ---- style partials ----
    const float lwv = lw[(size_t)o * WD_ + i];
    float p[B_];
#pragma unroll
    for (int b = 0; b < B_; b++) p[b] = w[b * WD_ + i] * lwv;
#pragma unroll
    for (int b = 0; b < B_; b++)
#pragma unroll
        for (int off = 16; off; off >>= 1)
            p[b] += __shfl_down_sync(0xFFFFFFFFu, p[b], off);
    const int wid = i >> 5, lane = i & 31;
    if (lane == 0)
#pragma unroll
        for (int b = 0; b < B_; b++) red[wid][b] = p[b];

    // ---- U and S ----
    const float* g = cw + ((size_t)o * C_ + i) * 9;
    float q[3][3];
    float s = 0.f;
#pragma unroll
    for (int r = 0; r < 3; r++)
#pragma unroll
        for (int c = 0; c < 3; c++) { q[r][c] = g[r * 3 + c]; s = fmaf(q[r][c], q[r][c], s); }
    g_S[o * C_ + i] = s;
    float t[4][3];
#pragma unroll
    for (int c = 0; c < 3; c++) {
        t[0][c] = q[0][c];
        t[1][c] = 0.5f * (q[0][c] + q[1][c] + q[2][c]);
        t[2][c] = 0.5f * (q[0][c] - q[1][c] + q[2][c]);
        t[3][c] = q[2][c];
    }
    __half* up = g_U + (size_t)o * C_ + i;
    const size_t ustr = (size_t)C_ * C_;
#pragma unroll
    for (int r = 0; r < 4; r++) {
        float u0 = t[r][0];
        float u1 = 0.5f * (t[r][0] + t[r][1] + t[r][2]);
        float u2 = 0.5f * (t[r][0] - t[r][1] + t[r][2]);
        float u3 = t[r][2];
        up[0]        = __float2half_rn(u0);
        up[ustr]     = __float2half_rn(u1);
        up[2 * ustr] = __float2half_rn(u2);
        up[3 * ustr] = __float2half_rn(u3);
        up += 4 * ustr;
    }

    // ---- style finalize ----
    __syncthreads();
    if (i < B_) {
        float acc = lb[o];
#pragma unroll
        for (int k = 0; k < 16; k++) acc += red[k][i];
        g_style[i * C_ + o] = acc;
    }
}

// ---------------- Winograd input transform: V = B^T d B (style folded) ----------------
__global__ void __launch_bounds__(256)
wino_x_kernel(const float* __restrict__ x) {
    __shared__ float xs[4][32][71];
    const int b = blockIdx.z, chg = blockIdx.y * 32, ty = blockIdx.x;
    const int tid = threadIdx.x;
    const float* xb = x + ((size_t)(b * C_ + chg)) * HW_;
    const int y0 = ty * 2 - 1;

    {   // main: cols 0..63 (gx = col-1): per-thread col/gx constant
        const int col = tid & 63;
        const int gx  = col - 1;
        const bool gxok = (unsigned)gx < W64;
#pragma unroll
        for (int j = 0; j < 32; j++) {
            int u  = (tid >> 6) + j * 4;   // 0..127 (r, ch) pairs
            int ch = u & 31;
            int r  = u >> 5;
            int y  = y0 + r;
            float v = 0.f;
            if (gxok && (unsigned)y < W64)
                v = xb[(size_t)ch * HW_ + y * W64 + gx];
            xs[r][ch][col] = v;
        }
    }
    {   // residue: cols 64,65 (gx 63,64)
        int c2 = tid & 1;
        int ch = (tid >> 1) & 31;
        int r  = tid >> 6;
        int y  = y0 + r;
        int gx = 63 + c2;
        float v = 0.f;
        if ((unsigned)y < W64 && (unsigned)gx < W64)
            v = xb[(size_t)ch * HW_ + y * W64 + gx];
        xs[r][ch][64 + c2] = v;
    }
    __syncthreads();

    const int tx  = tid >> 3;          // 0..31 tile col
    const int ch4 = (tid & 7) * 4;     // 0,4,...,28
    const int n   = b * 1024 + ty * 32 + tx;

    unsigned short hs[NCF][4];
#pragma unroll
    for (int cc = 0; cc < 4; cc++) {
        const int ch = ch4 + cc;
        const float st = g_style[b * C_ + chg + ch];
        float d[4][4];
#pragma unroll
        for (int r = 0; r < 4; r++)
#pragma unroll
            for (int c = 0; c < 4; c++) d[r][c] = xs[r][ch][2 * tx + c];
        float wv[4][4];
#pragma unroll
        for (int c = 0; c < 4; c++) {
            wv[0][c] = d[0][c] - d[2][c];
            wv[1][c] = d[1][c] + d[2][c];
            wv[2][c] = d[2][c] - d[1][c];
            wv[3][c] = d[1][c] - d[3][c];
        }
#pragma unroll
        for (int r = 0; r < 4; r++) {
            float v0 = wv[r][0] - wv[r][2];
            float v1 = wv[r][1] + wv[r][2];
            float v2 = wv[r][2] - wv[r][1];
            float v3 = wv[r][1] - wv[r][3];
            hs[r * 4 + 0][cc] = __half_as_ushort(__float2half_rn(v0 * st));
            hs[r * 4 + 1][cc] = __half_as_ushort(__float2half_rn(v1 * st));
            hs[r * 4 + 2][cc] = __half_as_ushort(__float2half_rn(v2 * st));
            hs[r * 4 + 3][cc] = __half_as_ushort(__float2half_rn(v3 * st));
        }
    }
    __half* vp = g_V + (size_t)n * C_ + chg + ch4;
    const size_t pstr = (size_t)NT_ * C_;
#pragma unroll
    for (int c = 0; c < NCF; c++) {
        uint2 val;
        val.x = (uint32_t)hs[c][0] | ((uint32_t)hs[c][1] << 16);
        val.y = (uint32_t)hs[c][2] | ((uint32_t)hs[c][3] << 16);
        *(uint2*)vp = val;
        vp += pstr;
    }
}

// ---------------- Winograd GEMM: M[oc][coef][n] = U[coef] @ V[coef]^T ----------------
#define STR    72
#define TILE_H (128 * STR)                 // 9216 halves per tile
#define STAGE_B (2 * TILE_H * 2)           // A + B per stage = 36864 bytes
#define NSTAGE 3
#define SMEM_BYTES (NSTAGE * STAGE_B)      // 110592

__global__ void __launch_bounds__(256, 2)
wino_gemm_kernel() {
    extern __shared__ __half smh[];
    const int tid  = threadIdx.x;
    const int coef = blockIdx.z;
    const int oc0  = blockIdx.y * 128;
    const int n0   = blockIdx.x * 128;
    const int lane = tid & 31;
    const int wrp  = tid >> 5;
    const int wm   = wrp & 1;
    const int wn   = wrp >> 1;
    const int qr   = lane >> 2;
    const int qc   = lane & 3;
    const int fr   = tid >> 2;             // 0..63
    const int fq   = (tid & 3) * 16;       // half offset in 64-ch chunk

    const __half* Ag = g_U + ((size_t)coef * C_ + oc0) * C_;
    const __half* Bg = g_V + ((size_t)coef * NT_ + n0) * C_;
    const uint32_t sbase = smem_u32(smh);

    float acc[4][4][4];
#pragma unroll
    for (int mt = 0; mt < 4; mt++)
#pragma unroll
        for (int nt = 0; nt < 4; nt++)
#pragma unroll
            for (int r = 0; r < 4; r++) acc[mt][nt][r] = 0.f;

    auto issue = [&](int it) {
        const int s   = it % NSTAGE;
        const int ci0 = it << 6;
        const uint32_t stA = sbase + (uint32_t)s * STAGE_B;
        const uint32_t stB = stA + TILE_H * 2;
        const __half* Ab = Ag + (size_t)fr * C_ + ci0 + fq;
        const __half* Bb = Bg + (size_t)fr * C_ + ci0 + fq;
        cp16(stA + (uint32_t)(fr * STR + fq) * 2, Ab);
        cp16(stA + (uint32_t)(fr * STR + fq + 8) * 2, Ab + 8);
        cp16(stA + (uint32_t)((fr + 64) * STR + fq) * 2, Ab + (size_t)64 * C_);
        cp16(stA + (uint32_t)((fr + 64) * STR + fq + 8) * 2, Ab + (size_t)64 * C_ + 8);
        cp16(stB + (uint32_t)(fr * STR + fq) * 2, Bb);
        cp16(stB + (uint32_t)(fr * STR + fq + 8) * 2, Bb + 8);
        cp16(stB + (uint32_t)((fr + 64) * STR + fq) * 2, Bb + (size_t)64 * C_);
        cp16(stB + (uint32_t)((fr + 64) * STR + fq + 8) * 2, Bb + (size_t)64 * C_ + 8);
        cp_commit();
    };

    issue(0);
    issue(1);

    for (int it = 0; it < 8; it++) {
        if (it + 2 < 8) { issue(it + 2); cp_wait<1>(); }
        else            { cp_wait<0>(); }
        __syncthreads();

        const uint32_t stA = sbase + (uint32_t)(it % NSTAGE) * STAGE_B;
        const uint32_t stB = stA + TILE_H * 2;

#pragma unroll
        for (int ks = 0; ks < 4; ks++) {
            const int k0 = ks * 16;
            uint32_t a[4][4], bf[2][4];
#pragma unroll
            for (int mt = 0; mt < 4; mt++) {
                int row  = wm * 64 + mt * 16 + (lane & 15);
                int colh = k0 + ((lane >> 4) << 3);
                ldsm4(a[mt], stA + (uint32_t)(row * STR + colh) * 2);
            }
#pragma unroll
            for (int pp = 0; pp < 2; pp++) {
                int sub  = lane >> 3;
                int n    = wn * 32 + (pp * 2 + (sub >> 1)) * 8 + (lane & 7);
                int colh = k0 + ((sub & 1) << 3);
                ldsm4(bf[pp], stB + (uint32_t)(n * STR + colh) * 2);
            }
#pragma unroll
            for (int mt = 0; mt < 4; mt++) {
#pragma unroll
                for (int nt = 0; nt < 4; nt++)
                    mma_f16(acc[mt][nt], a[mt], &bf[nt >> 1][(nt & 1) * 2]);
            }
        }
        __syncthreads();
    }

    // epilogue: store M[oc][coef][n] as fp16 (oc-major layout)
#pragma unroll
    for (int mt = 0; mt < 4; mt++) {
        const int oc_r = oc0 + wm * 64 + mt * 16 + qr;
        __half* o0 = g_M + ((size_t)(oc_r * NCF + coef)) * NT_ + n0 + wn * 32 + qc * 2;
        __half* o1 = o0 + (size_t)8 * NCF * NT_;
#pragma unroll
        for (int nt = 0; nt < 4; nt++) {
            *(__half2*)(o0 + nt * 8) = __floats2half2_rn(acc[mt][nt][0], acc[mt][nt][1]);
            *(__half2*)(o1 + nt * 8) = __floats2half2_rn(acc[mt][nt][2], acc[mt][nt][3]);
        }
    }
}

// ---------------- inverse transform + inline rdenom ----------------
// Block = one (b, oc) pair: rdenom computed by block reduction, then each
// thread handles 4 adjacent tiles: 16 x 8B plane loads (32KB apart, 512KB
// window), float4 output stores.
__global__ void __launch_bounds__(256)
wino_inv_kernel(float* __restrict__ out) {
    __shared__ float sred[8];
    __shared__ float srd;
    const int b   = blockIdx.x;            // 0..15 (block covers exactly one b)
    const int oc  = blockIdx.y;
    const int tid = threadIdx.x;

    // rdenom[b,oc] = rsqrt(sum_i S[oc,i]*style[b,i]^2 + eps)
    {
        float2 Sv = *(const float2*)(g_S + oc * C_ + tid * 2);
        float2 st = *(const float2*)(g_style + b * C_ + tid * 2);
        float pp = Sv.x * st.x * st.x + Sv.y * st.y * st.y;
#pragma unroll
        for (int off = 16; off; off >>= 1)
            pp += __shfl_down_sync(0xFFFFFFFFu, pp, off);
        if ((tid & 31) == 0) sred[tid >> 5] = pp;
        __syncthreads();
        if (tid == 0) {
            float a = EPS_;
#pragma unroll
            for (int k = 0; k < 8; k++) a += sred[k];
            srd = rsqrtf(a);
        }
        __syncthreads();
    }
    const float rd = srd;

    const int n  = b * 1024 + tid * 4;     // 4 tiles per thread
    const int t  = tid * 4;                // tile index within image
    const int ty = t >> 5, tx = t & 31;

    float m[4][16];
    const __half* mp = g_M + (size_t)oc * NCF * NT_ + n;
#pragma unroll
    for (int c = 0; c < NCF; c++) {
        uint2 raw = *(const uint2*)mp;
        __half2 h0 = *reinterpret_cast<__half2*>(&raw.x);
        __half2 h1 = *reinterpret_cast<__half2*>(&raw.y);
        float2 f0 = __half22float2(h0), f1 = __half22float2(h1);
        m[0][c] = f0.x; m[1][c] = f0.y; m[2][c] = f1.x; m[3][c] = f1.y;
        mp += NT_;
    }

    float r0[8], r1[8];
#pragma unroll
    for (int j = 0; j < 4; j++) {
        float z0[4], z1[4];
#pragma unroll
        for (int k = 0; k < 4; k++) {
            z0[k] = m[j][k * 4 + 0] + m[j][k * 4 + 1] + m[j][k * 4 + 2];
            z1[k] = m[j][k * 4 + 1] - m[j][k * 4 + 2] - m[j][k * 4 + 3];
        }
        r0[2 * j + 0] = (z0[0] + z0[1] + z0[2]) * rd;
        r0[2 * j + 1] = (z1[0] + z1[1] + z1[2]) * rd;
        r1[2 * j + 0] = (z0[1] - z0[2] - z0[3]) * rd;
        r1[2 * j + 1] = (z1[1] - z1[2] - z1[3]) * rd;
    }
    float* op = out + ((size_t)(b * C_ + oc)) * HW_ + (ty * 2) * W64 + tx * 2;
    *(float4*)op             = make_float4(r0[0], r0[1], r0[2], r0[3]);
    *(float4*)(op + 4)       = make_float4(r0[4], r0[5], r0[6], r0[7]);
    *(float4*)(op + W64)     = make_float4(r1[0], r1[1], r1[2], r1[3]);
    *(float4*)(op + W64 + 4) = make_float4(r1[4], r1[5], r1[6], r1[7]);
}

// ---------------- launch ----------------
// 4 kernels; profiled slot = launch index 3 -> wino_inv.
extern "C" void kernel_launch(void* const* d_in, const int* in_sizes, int n_in,
                              void* d_out, int out_size) {
    const float* x  = (const float*)d_in[0];   // (16,512,64,64)
    const float* w  = (const float*)d_in[1];   // (16,512)
    const float* cw = (const float*)d_in[2];   // (512,512,3,3)
    const float* lw = (const float*)d_in[3];   // (512,512)
    const float* lb = (const float*)d_in[4];   // (512,)
    float* out = (float*)d_out;                // (16,512,64,64) fp32

    cudaFuncSetAttribute(wino_gemm_kernel,
                         cudaFuncAttributeMaxDynamicSharedMemorySize, SMEM_BYTES);

    wino_w_kernel<<<C_, C_>>>(cw, w, lw, lb);                  // 0 (U + S + style)
    wino_x_kernel<<<dim3(32, C_ / 32, B_), 256>>>(x);          // 1
    wino_gemm_kernel<<<dim3(NT_ / 128, C_ / 128, NCF), 256, SMEM_BYTES>>>();  // 2
    wino_inv_kernel<<<dim3(B_, C_), 256>>>(out);               // 3 (profiled)
}